// round 16
// baseline (speedup 1.0000x reference)
#include <cuda_runtime.h>
#include <cuda_fp16.h>
#include <stdint.h>

#define B 4
#define S 2048
#define H 8
#define E 64
#define BH (B*H)
#define FQ 72   // smem row stride (halves)

// ---------------------------------------------------------------------------
// Device scratch (allocation-free)
// ---------------------------------------------------------------------------
__device__ __half g_qh[(size_t)BH*S*E];   // fp16 of 0.125*Qproj [bh][s][e]
__device__ __half g_kh[(size_t)BH*S*E];   // fp16 of Kproj
__device__ __half g_vh[(size_t)BH*E*S];   // fp16 of Vproj, transposed [bh][e][s]

// ---------------------------------------------------------------------------
// MMA helpers
// ---------------------------------------------------------------------------
__device__ __forceinline__ uint32_t smem_to_u32(const void* p) {
    uint32_t a;
    asm("{ .reg .u64 t; cvta.to.shared.u64 t, %1; cvt.u32.u64 %0, t; }" : "=r"(a) : "l"(p));
    return a;
}
__device__ __forceinline__ uint32_t pack_h2(float a, float b) {
    return (uint32_t)__half_as_ushort(__float2half_rn(a)) |
           ((uint32_t)__half_as_ushort(__float2half_rn(b)) << 16);
}
#define LDSM_X4(R0, R1, R2, R3, ADDR) \
    asm volatile("ldmatrix.sync.aligned.m8n8.x4.shared.b16 {%0,%1,%2,%3}, [%4];" \
                 : "=r"(R0), "=r"(R1), "=r"(R2), "=r"(R3) : "r"(ADDR))
#define MMA16816(C, A0, A1, A2, A3, B0, B1) \
    asm volatile("mma.sync.aligned.m16n8k16.row.col.f32.f16.f16.f32 " \
                 "{%0,%1,%2,%3}, {%4,%5,%6,%7}, {%8,%9}, {%0,%1,%2,%3};" \
                 : "+f"((C)[0]), "+f"((C)[1]), "+f"((C)[2]), "+f"((C)[3]) \
                 : "r"(A0), "r"(A1), "r"(A2), "r"(A3), "r"(B0), "r"(B1))

// ---------------------------------------------------------------------------
// Threefry2x32 (JAX partitionable) — validated rounds 1-14
// ---------------------------------------------------------------------------
__device__ __forceinline__ uint32_t rotl32(uint32_t v, int s) { return __funnelshift_l(v, v, s); }
__device__ __forceinline__ uint32_t threefry_mask_bits(uint32_t idx) {
    const uint32_t ks0 = 0u, ks1 = 42u, ks2 = 0x1BD11BDAu ^ 42u;
    uint32_t x0 = ks0, x1 = idx + ks1;
#define TFR(r) { x0 += x1; x1 = rotl32(x1, r); x1 ^= x0; }
    TFR(13) TFR(15) TFR(26) TFR(6)
    x0 += ks1; x1 += ks2 + 1u;
    TFR(17) TFR(29) TFR(16) TFR(24)
    x0 += ks2; x1 += ks0 + 2u;
    TFR(13) TFR(15) TFR(26) TFR(6)
    x0 += ks0; x1 += ks1 + 3u;
    TFR(17) TFR(29) TFR(16) TFR(24)
    x0 += ks1; x1 += ks2 + 4u;
    TFR(13) TFR(15) TFR(26) TFR(6)
    x0 += ks2; x1 += ks0 + 5u;
#undef TFR
    return x0 ^ x1;
}
#define KEEP_THRESH (7549747u << 9)
#define C512 6.2383246250395075f   // ln(512): fp16 range guard, cancels in normalization

// ---------------------------------------------------------------------------
// Kernel 1: QKV projection via HMMA (round-13/14 version, ~41us)
// ---------------------------------------------------------------------------
#define PW 72
#define SYW 133

__global__ __launch_bounds__(256, 3) void proj_kernel(
    const float* __restrict__ qin, const float* __restrict__ kin, const float* __restrict__ vin,
    const float* __restrict__ Wq, const float* __restrict__ bq,
    const float* __restrict__ Wk, const float* __restrict__ bk,
    const float* __restrict__ Wv, const float* __restrict__ bv)
{
    extern __shared__ char dyn[];
    __half* sWH = (__half*)dyn;
    __half* sWL = sWH + 64 * PW;
    __half* sXH = sWL + 64 * PW;
    __half* sXL = sXH + 128 * PW;
    float*  sbv = (float*)(sXL + 128 * PW);
    uint32_t* sY = (uint32_t*)sXH;

    const int tid = threadIdx.x;
    const int s0 = blockIdx.x * 128;
    const int bh = blockIdx.y;
    const int m  = blockIdx.z;
    const int b = bh >> 3, h = bh & 7;

    const float* __restrict__ xin  = (m == 0) ? qin : ((m == 1) ? kin : vin);
    const float* __restrict__ W    = (m == 0) ? Wq  : ((m == 1) ? Wk  : Wv);
    const float* __restrict__ bias = (m == 0) ? bq  : ((m == 1) ? bk  : bv);

    for (int i = tid; i < 1024; i += 256) {
        int r = i >> 4, c4 = (i & 15) * 4;
        float4 wv = ((const float4*)W)[i];
        __half h0 = __float2half_rn(wv.x), h1 = __float2half_rn(wv.y);
        __half h2 = __float2half_rn(wv.z), h3 = __float2half_rn(wv.w);
        *(__half2*)(sWH + r * PW + c4)     = __halves2half2(h0, h1);
        *(__half2*)(sWH + r * PW + c4 + 2) = __halves2half2(h2, h3);
        *(__half2*)(sWL + r * PW + c4) = __halves2half2(
            __float2half_rn(wv.x - __half2float(h0)), __float2half_rn(wv.y - __half2float(h1)));
        *(__half2*)(sWL + r * PW + c4 + 2) = __halves2half2(
            __float2half_rn(wv.z - __half2float(h2)), __float2half_rn(wv.w - __half2float(h3)));
    }
    if (tid < 64) sbv[tid] = bias[tid];
    for (int i = tid; i < 2048; i += 256) {
        int r = i >> 4, c4 = (i & 15) * 4;
        float4 xv = ((const float4*)(xin + ((size_t)((b * S + s0 + r) * H + h)) * 64))[i & 15];
        __half h0 = __float2half_rn(xv.x), h1 = __float2half_rn(xv.y);
        __half h2 = __float2half_rn(xv.z), h3 = __float2half_rn(xv.w);
        *(__half2*)(sXH + r * PW + c4)     = __halves2half2(h0, h1);
        *(__half2*)(sXH + r * PW + c4 + 2) = __halves2half2(h2, h3);
        *(__half2*)(sXL + r * PW + c4) = __halves2half2(
            __float2half_rn(xv.x - __half2float(h0)), __float2half_rn(xv.y - __half2float(h1)));
        *(__half2*)(sXL + r * PW + c4 + 2) = __halves2half2(
            __float2half_rn(xv.z - __half2float(h2)), __float2half_rn(xv.w - __half2float(h3)));
    }
    __syncthreads();

    const int w = tid >> 5, lane = tid & 31;
    const int lr = lane & 7, lg = lane >> 3;
    const int er = lane >> 2, ec = (lane & 3) * 2;

    const int arow = w * 16 + lr + (lg & 1) * 8;
    const int acol = (lg >> 1) * 8;
    const int brow = lr + (lg >> 1) * 8;
    const int bcol = (lg & 1) * 8;

    const uint32_t uXH = smem_to_u32(sXH), uXL = smem_to_u32(sXL);
    const uint32_t uWH = smem_to_u32(sWH), uWL = smem_to_u32(sWL);

    float acc[8][4];
    #pragma unroll
    for (int j = 0; j < 8; j++)
        #pragma unroll
        for (int l = 0; l < 4; l++) acc[j][l] = 0.0f;

    #pragma unroll
    for (int ks = 0; ks < 4; ks++) {
        uint32_t aH[4], aL[4], bH[4][4], bL[4][4];
        LDSM_X4(aH[0], aH[1], aH[2], aH[3],
                uXH + (uint32_t)((arow * PW + acol + ks * 16) * 2));
        #pragma unroll
        for (int nbp = 0; nbp < 4; nbp++)
            LDSM_X4(bH[nbp][0], bH[nbp][1], bH[nbp][2], bH[nbp][3],
                    uWH + (uint32_t)(((brow + nbp * 16) * PW + bcol + ks * 16) * 2));
        #pragma unroll
        for (int nb = 0; nb < 8; nb++)
            MMA16816(acc[nb], aH[0], aH[1], aH[2], aH[3],
                     bH[nb >> 1][(nb & 1) * 2], bH[nb >> 1][(nb & 1) * 2 + 1]);
        #pragma unroll
        for (int nbp = 0; nbp < 4; nbp++)
            LDSM_X4(bL[nbp][0], bL[nbp][1], bL[nbp][2], bL[nbp][3],
                    uWL + (uint32_t)(((brow + nbp * 16) * PW + bcol + ks * 16) * 2));
        #pragma unroll
        for (int nb = 0; nb < 8; nb++)
            MMA16816(acc[nb], aH[0], aH[1], aH[2], aH[3],
                     bL[nb >> 1][(nb & 1) * 2], bL[nb >> 1][(nb & 1) * 2 + 1]);
        LDSM_X4(aL[0], aL[1], aL[2], aL[3],
                uXL + (uint32_t)((arow * PW + acol + ks * 16) * 2));
        #pragma unroll
        for (int nb = 0; nb < 8; nb++)
            MMA16816(acc[nb], aL[0], aL[1], aL[2], aL[3],
                     bH[nb >> 1][(nb & 1) * 2], bH[nb >> 1][(nb & 1) * 2 + 1]);
    }

    const float qs = (m == 0) ? 0.125f : 1.0f;
    const int row0 = w * 16 + er;

    if (m < 2) {
        __half* dh = ((m == 0) ? g_qh : g_kh) + ((size_t)bh * S + s0) * 64;
        #pragma unroll
        for (int nb = 0; nb < 8; nb++) {
            const int col = nb * 8 + ec;
            const float b0 = sbv[col], b1 = sbv[col + 1];
            #pragma unroll
            for (int rr = 0; rr < 2; rr++) {
                const int row = row0 + rr * 8;
                float v0 = (acc[nb][rr * 2 + 0] + b0) * qs;
                float v1 = (acc[nb][rr * 2 + 1] + b1) * qs;
                *(__half2*)(dh + (size_t)row * 64 + col) =
                    __halves2half2(__float2half_rn(v0), __float2half_rn(v1));
            }
        }
    } else {
        __syncthreads();
        #pragma unroll
        for (int nb = 0; nb < 8; nb++) {
            const int col = nb * 8 + ec;
            const float b0 = sbv[col], b1 = sbv[col + 1];
            #pragma unroll
            for (int rr = 0; rr < 2; rr++) {
                const int row = row0 + rr * 8;
                sY[col * SYW + row] =
                    (uint32_t)__half_as_ushort(__float2half_rn(acc[nb][rr*2+0] + b0));
                sY[(col + 1) * SYW + row] =
                    (uint32_t)__half_as_ushort(__float2half_rn(acc[nb][rr*2+1] + b1));
            }
        }
        __syncthreads();
        for (int i = tid; i < 1024; i += 256) {
            const int fr = i >> 4, c = i & 15;
            const int sb8 = c * 8;
            uint32_t y[8];
            #pragma unroll
            for (int j = 0; j < 8; j++) y[j] = sY[fr * SYW + sb8 + j];
            uint4 hv;
            hv.x = (y[0] & 0xffffu) | (y[1] << 16);
            hv.y = (y[2] & 0xffffu) | (y[3] << 16);
            hv.z = (y[4] & 0xffffu) | (y[5] << 16);
            hv.w = (y[6] & 0xffffu) | (y[7] << 16);
            *(uint4*)(g_vh + ((size_t)bh * 64 + fr) * S + s0 + sb8) = hv;
        }
    }
}
#define PROJ_SMEM ((2*64*PW + 2*128*PW) * 2 + 64 * 4)

// ---------------------------------------------------------------------------
// Kernel 2: FA2-style fused flash attention.
// CTA: 64q x one bh.  8 warps = 2(q-half 32q) x 4(k-quarter 16k).
// Each warp: private online softmax over its k-strip; QK C-frag reused
// directly as PV A-frag (register-resident attn); oacc 32q x 64e.
// Only 2 syncthreads per chunk (K/V staging).  4-way merge at the end.
// ---------------------------------------------------------------------------
__global__ __launch_bounds__(256) void flash_kernel(float* __restrict__ out)
{
    extern __shared__ char smraw[];
    __half* sQ  = (__half*)smraw;             // [64][FQ]
    __half* sK  = sQ + 64 * FQ;               // [64][FQ]
    __half* sV  = sK + 64 * FQ;               // [64][FQ]
    float*  sMm = (float*)(sV + 64 * FQ);     // [4][64] per-quarter row max
    float*  sLl = sMm + 256;                  // [4][64] per-quarter row sum
    float*  sIv = sLl + 256;                  // [64] final 1/(0.9 l)
    float*  fbuf = (float*)sK;                // [64][66] merge buffer (aliases sK+sV)

    const int tid = threadIdx.x;
    const int q0 = blockIdx.x * 64, bh = blockIdx.y;

    const __half* qhp = g_qh + ((size_t)bh * S + q0) * 64;
    const __half* khp = g_kh + (size_t)bh * S * 64;
    const __half* vhp = g_vh + (size_t)bh * 64 * S;

    for (int i = tid; i < 512; i += 256) {
        int r = i >> 3, cc = (i & 7) * 8;
        *(uint4*)(sQ + r * FQ + cc) = *(const uint4*)(qhp + r * 64 + cc);
    }

    const int w = tid >> 5, lane = tid & 31;
    const int qrow0 = (w >> 2) * 32;      // q-half
    const int kq = (w & 3) * 16;          // k-quarter within chunk
    const int lr = lane & 7, lg = lane >> 3;
    const int er = lane >> 2, ec = (lane & 3) * 2;

    const int arow = qrow0 + lr + (lg & 1) * 8;   // Q rows for LDSM
    const int acol = (lg >> 1) * 8;
    const int sbrow = kq + lr + (lg >> 1) * 8;    // K rows (score B)
    const int bcol = (lg & 1) * 8;
    const int vcol = kq + (lg & 1) * 8;           // V k-col (PV B)
    const int vrow = lr + (lg >> 1) * 8;          // V e-row base (+nt*16)

    const uint32_t uQ = smem_to_u32(sQ), uK = smem_to_u32(sK), uV = smem_to_u32(sV);

    const uint32_t ibase = (uint32_t)(bh * S + q0) * (uint32_t)S;

    float m[4] = {-1e30f, -1e30f, -1e30f, -1e30f};
    float l[4] = {0.0f, 0.0f, 0.0f, 0.0f};
    float oacc[2][8][4];
    #pragma unroll
    for (int i = 0; i < 2; i++)
        #pragma unroll
        for (int j = 0; j < 8; j++)
            #pragma unroll
            for (int k = 0; k < 4; k++) oacc[i][j][k] = 0.0f;

    for (int c = 0; c < 32; c++) {
        __syncthreads();   // prior chunk's LDSM reads of sK/sV done
        for (int i = tid; i < 512; i += 256) {
            int r = i >> 3, cc = (i & 7) * 8;
            *(uint4*)(sK + r * FQ + cc) = *(const uint4*)(khp + (size_t)(c * 64 + r) * 64 + cc);
            *(uint4*)(sV + r * FQ + cc) = *(const uint4*)(vhp + (size_t)r * S + c * 64 + cc);
        }
        __syncthreads();

        // ---- score MMA: warp strip 32q x 16k ----
        float acc[2][2][4];
        #pragma unroll
        for (int i = 0; i < 2; i++)
            #pragma unroll
            for (int j = 0; j < 2; j++)
                #pragma unroll
                for (int k = 0; k < 4; k++) acc[i][j][k] = 0.0f;
        #pragma unroll
        for (int ks = 0; ks < 4; ks++) {
            uint32_t a[2][4], bb[4];
            #pragma unroll
            for (int mt = 0; mt < 2; mt++)
                LDSM_X4(a[mt][0], a[mt][1], a[mt][2], a[mt][3],
                        uQ + (uint32_t)(((arow + mt * 16) * FQ + acol + ks * 16) * 2));
            LDSM_X4(bb[0], bb[1], bb[2], bb[3],
                    uK + (uint32_t)((sbrow * FQ + bcol + ks * 16) * 2));
            #pragma unroll
            for (int mt = 0; mt < 2; mt++)
                #pragma unroll
                for (int nb = 0; nb < 2; nb++)
                    MMA16816(acc[mt][nb], a[mt][0], a[mt][1], a[mt][2], a[mt][3],
                             bb[nb * 2], bb[nb * 2 + 1]);
        }

        // ---- per-warp chunk max (quad shuffle) ----
        float cm[4];
        #pragma unroll
        for (int mt = 0; mt < 2; mt++) {
            float m0 = fmaxf(fmaxf(acc[mt][0][0], acc[mt][0][1]),
                             fmaxf(acc[mt][1][0], acc[mt][1][1]));
            float m1 = fmaxf(fmaxf(acc[mt][0][2], acc[mt][0][3]),
                             fmaxf(acc[mt][1][2], acc[mt][1][3]));
            m0 = fmaxf(m0, __shfl_xor_sync(0xffffffffu, m0, 1));
            m0 = fmaxf(m0, __shfl_xor_sync(0xffffffffu, m0, 2));
            m1 = fmaxf(m1, __shfl_xor_sync(0xffffffffu, m1, 1));
            m1 = fmaxf(m1, __shfl_xor_sync(0xffffffffu, m1, 2));
            cm[mt * 2] = m0; cm[mt * 2 + 1] = m1;
        }

        // ---- online update: rescale factors ----
        float resc[4];
        #pragma unroll
        for (int rr = 0; rr < 4; rr++) {
            float mn = fmaxf(m[rr], cm[rr]);
            resc[rr] = __expf(m[rr] - mn);
            m[rr] = mn;
        }
        #pragma unroll
        for (int mt = 0; mt < 2; mt++)
            #pragma unroll
            for (int ne = 0; ne < 8; ne++) {
                oacc[mt][ne][0] *= resc[mt * 2];
                oacc[mt][ne][1] *= resc[mt * 2];
                oacc[mt][ne][2] *= resc[mt * 2 + 1];
                oacc[mt][ne][3] *= resc[mt * 2 + 1];
            }

        // ---- exp + row sums + threefry + pack to PV A-frags ----
        uint32_t apk[2][4];
        float sums[4] = {0.0f, 0.0f, 0.0f, 0.0f};
        #pragma unroll
        for (int mt = 0; mt < 2; mt++) {
            #pragma unroll
            for (int nb = 0; nb < 2; nb++) {
                float p0 = __expf(acc[mt][nb][0] - m[mt * 2] + C512);
                float p1 = __expf(acc[mt][nb][1] - m[mt * 2] + C512);
                float p2 = __expf(acc[mt][nb][2] - m[mt * 2 + 1] + C512);
                float p3 = __expf(acc[mt][nb][3] - m[mt * 2 + 1] + C512);
                sums[mt * 2]     += p0 + p1;
                sums[mt * 2 + 1] += p2 + p3;

                const uint32_t kg = (uint32_t)(c * 64 + kq + nb * 8 + ec);
                const uint32_t i0 = ibase + (uint32_t)(qrow0 + mt * 16 + er) * (uint32_t)S + kg;
                const uint32_t i1 = i0 + 8u * (uint32_t)S;
                if (threefry_mask_bits(i0)      >= KEEP_THRESH) p0 = 0.0f;
                if (threefry_mask_bits(i0 + 1u) >= KEEP_THRESH) p1 = 0.0f;
                if (threefry_mask_bits(i1)      >= KEEP_THRESH) p2 = 0.0f;
                if (threefry_mask_bits(i1 + 1u) >= KEEP_THRESH) p3 = 0.0f;

                // C->A identity: a0=(r,2t/2t+1)=nb:{c0,c1}; a1=(r+8)=nb:{c2,c3}
                apk[mt][nb * 2]     = pack_h2(p0, p1);
                apk[mt][nb * 2 + 1] = pack_h2(p2, p3);
            }
        }
        #pragma unroll
        for (int rr = 0; rr < 4; rr++) {
            float s = sums[rr];
            s += __shfl_xor_sync(0xffffffffu, s, 1);
            s += __shfl_xor_sync(0xffffffffu, s, 2);
            l[rr] = l[rr] * resc[rr] + s;
        }

        // ---- PV MMA: oacc += P(32q x 16k) @ V(16k x 64e) ----
        #pragma unroll
        for (int nt = 0; nt < 4; nt++) {
            uint32_t bf[4];
            LDSM_X4(bf[0], bf[1], bf[2], bf[3],
                    uV + (uint32_t)(((vrow + nt * 16) * FQ + vcol) * 2));
            #pragma unroll
            for (int mt = 0; mt < 2; mt++) {
                MMA16816(oacc[mt][nt * 2],     apk[mt][0], apk[mt][1], apk[mt][2], apk[mt][3],
                         bf[0], bf[1]);
                MMA16816(oacc[mt][nt * 2 + 1], apk[mt][0], apk[mt][1], apk[mt][2], apk[mt][3],
                         bf[2], bf[3]);
            }
        }
    }

    // ======================= merge across 4 k-quarter warps =======================
    const int R[4] = {qrow0 + er, qrow0 + er + 8, qrow0 + 16 + er, qrow0 + 16 + er + 8};
    if ((lane & 3) == 0) {
        #pragma unroll
        for (int rr = 0; rr < 4; rr++) {
            sMm[(w & 3) * 64 + R[rr]] = m[rr];
            sLl[(w & 3) * 64 + R[rr]] = l[rr];
        }
    }
    __syncthreads();

    float fac[4];
    #pragma unroll
    for (int rr = 0; rr < 4; rr++) {
        const int row = R[rr];
        float gm = fmaxf(fmaxf(sMm[row], sMm[64 + row]),
                         fmaxf(sMm[128 + row], sMm[192 + row]));
        float lt = sLl[row]       * __expf(sMm[row] - gm)
                 + sLl[64 + row]  * __expf(sMm[64 + row] - gm)
                 + sLl[128 + row] * __expf(sMm[128 + row] - gm)
                 + sLl[192 + row] * __expf(sMm[192 + row] - gm);
        fac[rr] = __expf(m[rr] - gm);
        if ((w & 3) == 0 && (lane & 3) == 0)
            sIv[row] = 1.0f / (0.9f * lt);
    }

    // scale oacc by per-row factor
    #pragma unroll
    for (int mt = 0; mt < 2; mt++)
        #pragma unroll
        for (int ne = 0; ne < 8; ne++) {
            oacc[mt][ne][0] *= fac[mt * 2];
            oacc[mt][ne][1] *= fac[mt * 2];
            oacc[mt][ne][2] *= fac[mt * 2 + 1];
            oacc[mt][ne][3] *= fac[mt * 2 + 1];
        }

    // 4-pass additive merge through fbuf (aliases sK/sV; first sync orders reads)
    #pragma unroll
    for (int j = 0; j < 4; j++) {
        __syncthreads();
        if ((w & 3) == j) {
            #pragma unroll
            for (int mt = 0; mt < 2; mt++)
                #pragma unroll
                for (int ne = 0; ne < 8; ne++) {
                    const int r0 = qrow0 + mt * 16 + er;
                    const int col = ne * 8 + ec;
                    if (j == 0) {
                        fbuf[r0 * 66 + col]           = oacc[mt][ne][0];
                        fbuf[r0 * 66 + col + 1]       = oacc[mt][ne][1];
                        fbuf[(r0 + 8) * 66 + col]     = oacc[mt][ne][2];
                        fbuf[(r0 + 8) * 66 + col + 1] = oacc[mt][ne][3];
                    } else {
                        fbuf[r0 * 66 + col]           += oacc[mt][ne][0];
                        fbuf[r0 * 66 + col + 1]       += oacc[mt][ne][1];
                        fbuf[(r0 + 8) * 66 + col]     += oacc[mt][ne][2];
                        fbuf[(r0 + 8) * 66 + col + 1] += oacc[mt][ne][3];
                    }
                }
        }
    }
    __syncthreads();

    // final write
    for (int i = tid; i < 4096; i += 256) {
        const int row = i >> 6, col = i & 63;
        out[((size_t)bh * S + q0 + row) * 64 + col] = fbuf[row * 66 + col] * sIv[row];
    }
}
#define FL_SMEM (3 * 64 * FQ * 2 + (256 + 256 + 64) * 4)

// ---------------------------------------------------------------------------
extern "C" void kernel_launch(void* const* d_in, const int* in_sizes, int n_in,
                              void* d_out, int out_size) {
    (void)in_sizes; (void)n_in; (void)out_size;
    const float* query = (const float*)d_in[0];
    const float* key   = (const float*)d_in[1];
    const float* value = (const float*)d_in[2];
    const float* Wq    = (const float*)d_in[3];
    const float* bq    = (const float*)d_in[4];
    const float* Wk    = (const float*)d_in[5];
    const float* bk    = (const float*)d_in[6];
    const float* Wv    = (const float*)d_in[7];
    const float* bv    = (const float*)d_in[8];
    float* out = (float*)d_out;

    cudaFuncSetAttribute(proj_kernel,  cudaFuncAttributeMaxDynamicSharedMemorySize, PROJ_SMEM);
    cudaFuncSetAttribute(flash_kernel, cudaFuncAttributeMaxDynamicSharedMemorySize, FL_SMEM);

    dim3 pg(S / 128, BH, 3);
    proj_kernel<<<pg, 256, PROJ_SMEM>>>(query, key, value, Wq, bq, Wk, bk, Wv, bv);

    dim3 fg(S / 64, BH);
    flash_kernel<<<fg, 256, FL_SMEM>>>(out);
}